// round 1
// baseline (speedup 1.0000x reference)
#include <cuda_runtime.h>
#include <math.h>

// Problem shape: B=32, H=512, W=512 (derive B from in_sizes at launch; arrays
// sized for the max B=32 seen in the dataset).
#define W_IMG 512
#define H_IMG 512
#define HW_IMG (W_IMG * H_IMG)
#define MAX_N (32 * HW_IMG)

// Scratch (no cudaMalloc allowed): union-find labels and per-root areas.
__device__ int g_label[MAX_N];
__device__ int g_area[MAX_N];
// Accumulators: 0 = sum_fg bce/(w+1), 1 = sum_bg bce, 2 = sum_fg w, 3 = N_fg
__device__ double g_acc[4];

// ---------------------------------------------------------------------------
// Union-find helpers (labels only decrease -> atomicMin union converges in
// one pass; find terminates since g_label[x] <= x always).
// ---------------------------------------------------------------------------
__device__ __forceinline__ int find_root(int x) {
    int p = g_label[x];
    while (p != x) {
        x = p;
        p = g_label[x];
    }
    return x;
}

__device__ __forceinline__ void merge(int a, int b) {
    bool done = false;
    do {
        a = find_root(a);
        b = find_root(b);
        if (a < b) { int t = a; a = b; b = t; }  // a = hi, b = lo
        if (a != b) {
            int old = atomicMin(&g_label[a], b);
            done = (old == a);
            a = old;  // if someone else lowered it, keep merging that root
        } else {
            done = true;
        }
    } while (!done);
}

// ---------------------------------------------------------------------------
// Kernels
// ---------------------------------------------------------------------------
__global__ void k_init(int n) {
    int stride = gridDim.x * blockDim.x;
    for (int i = blockIdx.x * blockDim.x + threadIdx.x; i < n; i += stride) {
        g_label[i] = i;
        g_area[i] = 0;
    }
    if (blockIdx.x == 0 && threadIdx.x < 4) g_acc[threadIdx.x] = 0.0;
}

__global__ void k_union(const float* __restrict__ tgt, int n) {
    int stride = gridDim.x * blockDim.x;
    for (int i = blockIdx.x * blockDim.x + threadIdx.x; i < n; i += stride) {
        if (tgt[i] > 0.0f) {
            int x = i & (W_IMG - 1);
            int y = (i / W_IMG) & (H_IMG - 1);
            if (x > 0 && tgt[i - 1] > 0.0f)      merge(i, i - 1);
            if (y > 0 && tgt[i - W_IMG] > 0.0f)  merge(i, i - W_IMG);
        }
    }
}

__global__ void k_flatten_area(const float* __restrict__ tgt, int n) {
    int stride = gridDim.x * blockDim.x;
    for (int i = blockIdx.x * blockDim.x + threadIdx.x; i < n; i += stride) {
        int r = find_root(i);
        g_label[i] = r;  // path compress to final root
        if (tgt[i] > 0.0f) atomicAdd(&g_area[r], 1);
    }
}

__device__ __forceinline__ double warp_sum(double v) {
#pragma unroll
    for (int off = 16; off > 0; off >>= 1)
        v += __shfl_down_sync(0xFFFFFFFFu, v, off);
    return v;
}

__global__ void k_loss(const float* __restrict__ in,
                       const float* __restrict__ tgt, int n) {
    double s0 = 0.0, s1 = 0.0, s2 = 0.0, s3 = 0.0;
    int stride = gridDim.x * blockDim.x;
    for (int i = blockIdx.x * blockDim.x + threadIdx.x; i < n; i += stride) {
        float x = in[i];
        float t = tgt[i];
        // numerically-stable bce-with-logits, reduction='none'
        float bce = fmaxf(x, 0.0f) - x * t + log1pf(expf(-fabsf(x)));
        if (t > 0.0f) {
            float w = sqrtf((float)g_area[g_label[i]]);
            s0 += (double)(bce / (w + 1.0f));
            s2 += (double)w;
            s3 += 1.0;
        } else {
            s1 += (double)bce;
        }
    }

    // block reduction: warp shuffle, then cross-warp via shared
    __shared__ double sh[4][8];  // up to 8 warps (256 threads)
    int lane = threadIdx.x & 31;
    int warp = threadIdx.x >> 5;
    s0 = warp_sum(s0); s1 = warp_sum(s1); s2 = warp_sum(s2); s3 = warp_sum(s3);
    if (lane == 0) { sh[0][warp] = s0; sh[1][warp] = s1; sh[2][warp] = s2; sh[3][warp] = s3; }
    __syncthreads();
    int nw = blockDim.x >> 5;
    if (warp == 0) {
        double v0 = (lane < nw) ? sh[0][lane] : 0.0;
        double v1 = (lane < nw) ? sh[1][lane] : 0.0;
        double v2 = (lane < nw) ? sh[2][lane] : 0.0;
        double v3 = (lane < nw) ? sh[3][lane] : 0.0;
        v0 = warp_sum(v0); v1 = warp_sum(v1); v2 = warp_sum(v2); v3 = warp_sum(v3);
        if (lane == 0) {
            atomicAdd(&g_acc[0], v0);
            atomicAdd(&g_acc[1], v1);
            atomicAdd(&g_acc[2], v2);
            atomicAdd(&g_acc[3], v3);
        }
    }
}

__global__ void k_final(float* __restrict__ out, double inv_n) {
    double nfg = g_acc[3];
    double mean_nz = g_acc[2] / (nfg > 0.0 ? nfg : 1.0);
    double loss = (g_acc[0] + g_acc[1] / (mean_nz + 1.0)) * inv_n;
    out[0] = (float)loss;
}

// ---------------------------------------------------------------------------
// Launch
// ---------------------------------------------------------------------------
extern "C" void kernel_launch(void* const* d_in, const int* in_sizes, int n_in,
                              void* d_out, int out_size) {
    const float* inputs  = (const float*)d_in[0];
    const float* targets = (const float*)d_in[1];
    float* out = (float*)d_out;

    int n = in_sizes[0];  // B*H*W
    const int threads = 256;
    const int blocks = 148 * 8;  // grid-stride, keeps final atomics cheap

    k_init<<<blocks, threads>>>(n);
    k_union<<<blocks, threads>>>(targets, n);
    k_flatten_area<<<blocks, threads>>>(targets, n);
    k_loss<<<blocks, threads>>>(inputs, targets, n);
    k_final<<<1, 1>>>(out, 1.0 / (double)n);
}

// round 2
// speedup vs baseline: 1.3589x; 1.3589x over previous
#include <cuda_runtime.h>
#include <math.h>

#define W_IMG 512
#define H_IMG 512
#define HW_IMG (W_IMG * H_IMG)
#define MAX_N (32 * HW_IMG)

// Scratch: union-find labels and per-root areas (no cudaMalloc allowed).
__device__ int g_label[MAX_N];
__device__ int g_area[MAX_N];
// 0 = sum_fg bce/(w+1), 1 = sum_bg bce, 2 = sum_fg w, 3 = N_fg
__device__ double g_acc[4];

// ---------------------------------------------------------------------------
// Union-find (labels only decrease -> atomicMin union converges in one pass)
// ---------------------------------------------------------------------------
__device__ __forceinline__ int find_root(int x) {
    int p = g_label[x];
    while (p != x) {
        x = p;
        p = g_label[x];
    }
    return x;
}

__device__ __forceinline__ void merge(int a, int b) {
    bool done = false;
    do {
        a = find_root(a);
        b = find_root(b);
        if (a < b) { int t = a; a = b; b = t; }  // a = hi, b = lo
        if (a != b) {
            int old = atomicMin(&g_label[a], b);
            done = (old == a);
            a = old;
        } else {
            done = true;
        }
    } while (!done);
}

// ---------------------------------------------------------------------------
// Kernels (n4 = n/4; all vector loops, W divisible by 4)
// ---------------------------------------------------------------------------
__global__ void k_init(int n4) {
    int stride = gridDim.x * blockDim.x;
    int4* lab4 = (int4*)g_label;
    int4* area4 = (int4*)g_area;
    for (int j = blockIdx.x * blockDim.x + threadIdx.x; j < n4; j += stride) {
        int i = j << 2;
        lab4[j] = make_int4(i, i + 1, i + 2, i + 3);
        area4[j] = make_int4(0, 0, 0, 0);
    }
    if (blockIdx.x == 0 && threadIdx.x < 4) g_acc[threadIdx.x] = 0.0;
}

__global__ void k_union(const float* __restrict__ tgt, int n4) {
    int stride = gridDim.x * blockDim.x;
    const float4* tgt4 = (const float4*)tgt;
    const int W4 = W_IMG / 4;
    for (int j = blockIdx.x * blockDim.x + threadIdx.x; j < n4; j += stride) {
        float4 t4 = __ldg(&tgt4[j]);
        float t[4] = {t4.x, t4.y, t4.z, t4.w};
        if (t[0] <= 0.f && t[1] <= 0.f && t[2] <= 0.f && t[3] <= 0.f) continue;

        int i = j << 2;
        int x0 = i & (W_IMG - 1);
        int y  = (i >> 9) & (H_IMG - 1);

        float left = (x0 > 0) ? __ldg(&tgt[i - 1]) : 0.f;
        float4 u4 = (y > 0) ? __ldg(&tgt4[j - W4]) : make_float4(0, 0, 0, 0);
        float up[4] = {u4.x, u4.y, u4.z, u4.w};

#pragma unroll
        for (int k = 0; k < 4; k++) {
            if (t[k] > 0.f) {
                float lnb = (k > 0) ? t[k - 1] : left;
                if (lnb > 0.f)   merge(i + k, i + k - 1);
                if (up[k] > 0.f) merge(i + k, i + k - W_IMG);
            }
        }
    }
}

__global__ void k_flatten_area(const float* __restrict__ tgt, int n4) {
    int stride = gridDim.x * blockDim.x;
    const float4* tgt4 = (const float4*)tgt;
    for (int j = blockIdx.x * blockDim.x + threadIdx.x; j < n4; j += stride) {
        float4 t4 = __ldg(&tgt4[j]);
        float t[4] = {t4.x, t4.y, t4.z, t4.w};
        int i = j << 2;
#pragma unroll
        for (int k = 0; k < 4; k++) {
            if (t[k] > 0.f) {
                int r = find_root(i + k);
                g_label[i + k] = r;          // compress to final root
                atomicAdd(&g_area[r], 1);
            }
        }
    }
}

__device__ __forceinline__ double warp_sum(double v) {
#pragma unroll
    for (int off = 16; off > 0; off >>= 1)
        v += __shfl_down_sync(0xFFFFFFFFu, v, off);
    return v;
}

__global__ void k_loss(const float* __restrict__ in,
                       const float* __restrict__ tgt, int n4) {
    double s0 = 0.0, s1 = 0.0, s2 = 0.0, s3 = 0.0;
    int stride = gridDim.x * blockDim.x;
    const float4* in4 = (const float4*)in;
    const float4* tgt4 = (const float4*)tgt;
    const int4* lab4 = (const int4*)g_label;

    for (int j = blockIdx.x * blockDim.x + threadIdx.x; j < n4; j += stride) {
        float4 x4 = __ldg(&in4[j]);
        float4 t4 = __ldg(&tgt4[j]);
        int4  l4 = __ldg(&lab4[j]);

        // 4 independent area gathers (bg entries are zero-init, value unused)
        int a0 = __ldg(&g_area[l4.x]);
        int a1 = __ldg(&g_area[l4.y]);
        int a2 = __ldg(&g_area[l4.z]);
        int a3 = __ldg(&g_area[l4.w]);

        float x[4] = {x4.x, x4.y, x4.z, x4.w};
        float t[4] = {t4.x, t4.y, t4.z, t4.w};
        int   a[4] = {a0, a1, a2, a3};

        float f0 = 0.f, f1 = 0.f, f2 = 0.f, f3 = 0.f;
#pragma unroll
        for (int k = 0; k < 4; k++) {
            float bce = fmaxf(x[k], 0.f) - x[k] * t[k] + log1pf(__expf(-fabsf(x[k])));
            if (t[k] > 0.f) {
                float w = sqrtf((float)a[k]);
                f0 += bce / (w + 1.f);
                f2 += w;
                f3 += 1.f;
            } else {
                f1 += bce;
            }
        }
        s0 += (double)f0; s1 += (double)f1; s2 += (double)f2; s3 += (double)f3;
    }

    __shared__ double sh[4][8];
    int lane = threadIdx.x & 31;
    int warp = threadIdx.x >> 5;
    s0 = warp_sum(s0); s1 = warp_sum(s1); s2 = warp_sum(s2); s3 = warp_sum(s3);
    if (lane == 0) { sh[0][warp] = s0; sh[1][warp] = s1; sh[2][warp] = s2; sh[3][warp] = s3; }
    __syncthreads();
    int nw = blockDim.x >> 5;
    if (warp == 0) {
        double v0 = (lane < nw) ? sh[0][lane] : 0.0;
        double v1 = (lane < nw) ? sh[1][lane] : 0.0;
        double v2 = (lane < nw) ? sh[2][lane] : 0.0;
        double v3 = (lane < nw) ? sh[3][lane] : 0.0;
        v0 = warp_sum(v0); v1 = warp_sum(v1); v2 = warp_sum(v2); v3 = warp_sum(v3);
        if (lane == 0) {
            atomicAdd(&g_acc[0], v0);
            atomicAdd(&g_acc[1], v1);
            atomicAdd(&g_acc[2], v2);
            atomicAdd(&g_acc[3], v3);
        }
    }
}

__global__ void k_final(float* __restrict__ out, double inv_n) {
    double nfg = g_acc[3];
    double mean_nz = g_acc[2] / (nfg > 0.0 ? nfg : 1.0);
    double loss = (g_acc[0] + g_acc[1] / (mean_nz + 1.0)) * inv_n;
    out[0] = (float)loss;
}

// ---------------------------------------------------------------------------
extern "C" void kernel_launch(void* const* d_in, const int* in_sizes, int n_in,
                              void* d_out, int out_size) {
    const float* inputs  = (const float*)d_in[0];
    const float* targets = (const float*)d_in[1];
    float* out = (float*)d_out;

    int n = in_sizes[0];
    int n4 = n >> 2;
    const int threads = 256;
    const int blocks = 148 * 8;

    k_init<<<blocks, threads>>>(n4);
    k_union<<<blocks, threads>>>(targets, n4);
    k_flatten_area<<<blocks, threads>>>(targets, n4);
    k_loss<<<blocks, threads>>>(inputs, targets, n4);
    k_final<<<1, 1>>>(out, 1.0 / (double)n);
}

// round 3
// speedup vs baseline: 1.5905x; 1.1704x over previous
#include <cuda_runtime.h>
#include <math.h>

#define W_IMG 512
#define H_IMG 512
#define HW_IMG (W_IMG * H_IMG)
#define MAX_N (32 * HW_IMG)
#define MAX_WORDS (MAX_N / 64)

// Scratch (no cudaMalloc allowed)
__device__ int g_label[MAX_N];                 // union-find / final per-pixel root (-1 = bg)
__device__ int g_area[MAX_N];                  // per-root component area
__device__ unsigned long long g_bits[MAX_WORDS];  // fg bitmask, 64 px/word
// 0 = sum_fg bce/(w+1), 1 = sum_bg bce, 2 = sum_fg w, 3 = N_fg
__device__ double g_acc[4];

// ---------------------------------------------------------------------------
// Union-find: nodes are within-word run-start pixel indices only.
// Labels only decrease -> atomicMin union converges in one pass.
// ---------------------------------------------------------------------------
__device__ __forceinline__ int find_root(int x) {
    int p = g_label[x];
    while (p != x) { x = p; p = g_label[x]; }
    return x;
}

__device__ __forceinline__ void merge(int a, int b) {
    bool done = false;
    do {
        a = find_root(a);
        b = find_root(b);
        if (a < b) { int t = a; a = b; b = t; }  // a = hi, b = lo
        if (a != b) {
            int old = atomicMin(&g_label[a], b);
            done = (old == a);
            a = old;
        } else {
            done = true;
        }
    } while (!done);
}

// Run start (bit position) of the run containing set bit k of mask m.
__device__ __forceinline__ int rs_in_word(unsigned long long m, int k) {
    unsigned long long below = (k == 0) ? 0ull : ((1ull << k) - 1ull);
    unsigned long long z = (~m) & below;            // zeros strictly below k
    return z ? (64 - __clzll(z)) : 0;               // highest zero + 1
}

// ---------------------------------------------------------------------------
// k_prep: build bitmask, init UF nodes at run starts, zero areas at run starts
// ---------------------------------------------------------------------------
__global__ void k_prep(const float* __restrict__ tgt, int nwords) {
    int w = blockIdx.x * blockDim.x + threadIdx.x;
    if (w < nwords) {
        const float4* t4 = (const float4*)tgt;
        int gbase = w * 16;
        unsigned long long m = 0ull;
#pragma unroll
        for (int g = 0; g < 16; g++) {
            float4 v = __ldg(&t4[gbase + g]);
            unsigned long long nib = 0ull;
            if (v.x > 0.f) nib |= 1ull;
            if (v.y > 0.f) nib |= 2ull;
            if (v.z > 0.f) nib |= 4ull;
            if (v.w > 0.f) nib |= 8ull;
            m |= nib << (g * 4);
        }
        g_bits[w] = m;
        int base = w << 6;
        unsigned long long r = m & ~(m << 1);       // within-word run starts
        while (r) {
            int k = __ffsll((long long)r) - 1;
            r &= r - 1;
            g_label[base + k] = base + k;
            g_area[base + k] = 0;
        }
    }
    if (blockIdx.x == 0 && threadIdx.x < 4) g_acc[threadIdx.x] = 0.0;
}

// ---------------------------------------------------------------------------
// k_union: bitmask-driven merges (run-level, boundary-reduced)
// ---------------------------------------------------------------------------
__global__ void k_union(int nwords) {
    int w = blockIdx.x * blockDim.x + threadIdx.x;
    if (w >= nwords) return;
    unsigned long long cur = g_bits[w];
    if (!cur) return;
    int base = w << 6;
    int wx = w & 7;                      // word-in-row (8 words per 512px row)
    int wy = (w >> 3) & (H_IMG - 1);     // row within image

    // horizontal cross-word merge (runs crossing the 64px word boundary)
    if (wx && (cur & 1ull)) {
        unsigned long long L = g_bits[w - 1];
        if (L >> 63) merge(base, ((w - 1) << 6) + rs_in_word(L, 63));
    }
    // vertical merges: one per overlap segment
    if (wy) {
        unsigned long long up = g_bits[w - 8];
        unsigned long long ov = cur & up;
        unsigned long long need = ov & ~(ov << 1);
        while (need) {
            int k = __ffsll((long long)need) - 1;
            need &= need - 1;
            merge(base + rs_in_word(cur, k),
                  ((w - 8) << 6) + rs_in_word(up, k));
        }
    }
}

// ---------------------------------------------------------------------------
// k_flatten: per run -> root + area (run-length atomics); write per-pixel
// labels (root, or -1 for bg) for the loss pass.
// ---------------------------------------------------------------------------
__global__ void k_flatten(int nwords) {
    int w = blockIdx.x * blockDim.x + threadIdx.x;
    if (w >= nwords) return;
    unsigned long long cur = g_bits[w];
    int base = w << 6;
    int4* lab4 = (int4*)g_label;
    int root = 0;
    int ov[4];
#pragma unroll
    for (int g = 0; g < 16; g++) {
#pragma unroll
        for (int lane = 0; lane < 4; lane++) {
            int k = g * 4 + lane;
            int v = -1;
            if ((cur >> k) & 1ull) {
                bool start = (k == 0) ? true : !((cur >> (k - 1)) & 1ull);
                if (start) {
                    root = find_root(base + k);
                    unsigned long long sh = cur >> k;
                    unsigned long long inv = ~sh;
                    int len = inv ? (__ffsll((long long)inv) - 1) : (64 - k);
                    atomicAdd(&g_area[root], len);
                }
                v = root;
            }
            ov[lane] = v;
        }
        lab4[w * 16 + g] = make_int4(ov[0], ov[1], ov[2], ov[3]);
    }
}

// ---------------------------------------------------------------------------
// k_loss: bce = softplus((1-2t)*x); fg detection via label sign.
// ---------------------------------------------------------------------------
__device__ __forceinline__ double warp_sum(double v) {
#pragma unroll
    for (int off = 16; off > 0; off >>= 1)
        v += __shfl_down_sync(0xFFFFFFFFu, v, off);
    return v;
}

__global__ void k_loss(const float* __restrict__ in, int n8) {
    double s0 = 0.0, s1 = 0.0, s2 = 0.0, s3 = 0.0;
    int u = blockIdx.x * blockDim.x + threadIdx.x;
    if (u < n8) {
        const float4* in4 = (const float4*)in;
        const int4* lab4 = (const int4*)g_label;
        float f0 = 0.f, f1 = 0.f, f2 = 0.f, f3 = 0.f;
#pragma unroll
        for (int g = 0; g < 2; g++) {
            int j = u * 2 + g;
            float4 x4 = __ldg(&in4[j]);
            int4 l4 = __ldg(&lab4[j]);
            float xs[4] = {x4.x, x4.y, x4.z, x4.w};
            int ls[4] = {l4.x, l4.y, l4.z, l4.w};
#pragma unroll
            for (int k = 0; k < 4; k++) {
                bool fg = ls[k] >= 0;
                float a = fg ? (float)__ldg(&g_area[ls[k]]) : 0.f;
                float s = fg ? -xs[k] : xs[k];
                float bce = __logf(1.f + __expf(s));   // softplus(s)
                if (fg) {
                    float wgt = sqrtf(a);
                    f0 += __fdividef(bce, wgt + 1.f);
                    f2 += wgt;
                    f3 += 1.f;
                } else {
                    f1 += bce;
                }
            }
        }
        s0 = f0; s1 = f1; s2 = f2; s3 = f3;
    }

    __shared__ double sh[4][8];
    int lane = threadIdx.x & 31;
    int warp = threadIdx.x >> 5;
    s0 = warp_sum(s0); s1 = warp_sum(s1); s2 = warp_sum(s2); s3 = warp_sum(s3);
    if (lane == 0) { sh[0][warp] = s0; sh[1][warp] = s1; sh[2][warp] = s2; sh[3][warp] = s3; }
    __syncthreads();
    int nw = blockDim.x >> 5;
    if (warp == 0) {
        double v0 = (lane < nw) ? sh[0][lane] : 0.0;
        double v1 = (lane < nw) ? sh[1][lane] : 0.0;
        double v2 = (lane < nw) ? sh[2][lane] : 0.0;
        double v3 = (lane < nw) ? sh[3][lane] : 0.0;
        v0 = warp_sum(v0); v1 = warp_sum(v1); v2 = warp_sum(v2); v3 = warp_sum(v3);
        if (lane == 0) {
            atomicAdd(&g_acc[0], v0);
            atomicAdd(&g_acc[1], v1);
            atomicAdd(&g_acc[2], v2);
            atomicAdd(&g_acc[3], v3);
        }
    }
}

__global__ void k_final(float* __restrict__ out, double inv_n) {
    double nfg = g_acc[3];
    double mean_nz = g_acc[2] / (nfg > 0.0 ? nfg : 1.0);
    double loss = (g_acc[0] + g_acc[1] / (mean_nz + 1.0)) * inv_n;
    out[0] = (float)loss;
}

// ---------------------------------------------------------------------------
extern "C" void kernel_launch(void* const* d_in, const int* in_sizes, int n_in,
                              void* d_out, int out_size) {
    const float* inputs  = (const float*)d_in[0];
    const float* targets = (const float*)d_in[1];
    float* out = (float*)d_out;

    int n = in_sizes[0];
    int nwords = n >> 6;
    int n8 = n >> 3;
    const int threads = 256;
    int wblocks = (nwords + threads - 1) / threads;
    int lblocks = (n8 + threads - 1) / threads;

    k_prep<<<wblocks, threads>>>(targets, nwords);
    k_union<<<wblocks, threads>>>(nwords);
    k_flatten<<<wblocks, threads>>>(nwords);
    k_loss<<<lblocks, threads>>>(inputs, n8);
    k_final<<<1, 1>>>(out, 1.0 / (double)n);
}

// round 4
// speedup vs baseline: 1.8982x; 1.1935x over previous
#include <cuda_runtime.h>
#include <math.h>

#define W_IMG 512
#define H_IMG 512
#define HW_IMG (W_IMG * H_IMG)
#define MAX_N (32 * HW_IMG)
#define MAX_WORDS (MAX_N / 64)

// Scratch (no cudaMalloc allowed)
__device__ int g_label[MAX_N];                    // UF parent (run-start nodes only)
__device__ int g_area[MAX_N];                     // per-root component area
__device__ unsigned long long g_bits[MAX_WORDS];  // fg bitmask, 64 px/word
// 0 = sum_fg bce/(w+1), 1 = sum_bg bce, 2 = sum_fg w, 3 = N_fg
__device__ double g_acc[4];

// ---------------------------------------------------------------------------
// Union-find (labels only decrease -> atomicMin union converges in one pass)
// ---------------------------------------------------------------------------
__device__ __forceinline__ int find_root(int x) {
    int p = g_label[x];
    while (p != x) { x = p; p = g_label[x]; }
    return x;
}

__device__ __forceinline__ void merge(int a, int b) {
    bool done = false;
    do {
        a = find_root(a);
        b = find_root(b);
        if (a < b) { int t = a; a = b; b = t; }
        if (a != b) {
            int old = atomicMin(&g_label[a], b);
            done = (old == a);
            a = old;
        } else {
            done = true;
        }
    } while (!done);
}

// Run start (bit position) of the run containing set bit k of mask m.
__device__ __forceinline__ int rs_in_word(unsigned long long m, int k) {
    unsigned long long below = (k == 0) ? 0ull : ((1ull << k) - 1ull);
    unsigned long long z = (~m) & below;
    return z ? (64 - __clzll(z)) : 0;
}

// Length of the run of ones in m starting at bit k.
__device__ __forceinline__ int run_len(unsigned long long m, int k) {
    unsigned long long inv = ~(m >> k);
    return inv ? (__ffsll((long long)inv) - 1) : (64 - k);
}

// ---------------------------------------------------------------------------
// k_prep: build bitmask, init UF nodes + areas at within-word run starts
// ---------------------------------------------------------------------------
__global__ void k_prep(const float* __restrict__ tgt, int nwords) {
    int w = blockIdx.x * blockDim.x + threadIdx.x;
    if (w < nwords) {
        const float4* t4 = (const float4*)tgt;
        int gbase = w * 16;
        unsigned long long m = 0ull;
#pragma unroll
        for (int g = 0; g < 16; g++) {
            float4 v = __ldg(&t4[gbase + g]);
            unsigned long long nib = 0ull;
            if (v.x > 0.f) nib |= 1ull;
            if (v.y > 0.f) nib |= 2ull;
            if (v.z > 0.f) nib |= 4ull;
            if (v.w > 0.f) nib |= 8ull;
            m |= nib << (g * 4);
        }
        g_bits[w] = m;
        int base = w << 6;
        unsigned long long r = m & ~(m << 1);
        while (r) {
            int k = __ffsll((long long)r) - 1;
            r &= r - 1;
            g_label[base + k] = base + k;
            g_area[base + k] = 0;
        }
    }
    if (blockIdx.x == 0 && threadIdx.x < 4) g_acc[threadIdx.x] = 0.0;
}

// ---------------------------------------------------------------------------
// k_union: bitmask-driven merges (run-level)
// ---------------------------------------------------------------------------
__global__ void k_union(int nwords) {
    int w = blockIdx.x * blockDim.x + threadIdx.x;
    if (w >= nwords) return;
    unsigned long long cur = g_bits[w];
    if (!cur) return;
    int base = w << 6;
    int wx = w & 7;
    int wy = (w >> 3) & (H_IMG - 1);

    if (wx && (cur & 1ull)) {
        unsigned long long L = g_bits[w - 1];
        if (L >> 63) merge(base, ((w - 1) << 6) + rs_in_word(L, 63));
    }
    if (wy) {
        unsigned long long up = g_bits[w - 8];
        unsigned long long ov = cur & up;
        unsigned long long need = ov & ~(ov << 1);
        while (need) {
            int k = __ffsll((long long)need) - 1;
            need &= need - 1;
            merge(base + rs_in_word(cur, k),
                  ((w - 8) << 6) + rs_in_word(up, k));
        }
    }
}

// ---------------------------------------------------------------------------
// k_area: per run -> final root (path-compress) + area accumulate
// ---------------------------------------------------------------------------
__global__ void k_area(int nwords) {
    int w = blockIdx.x * blockDim.x + threadIdx.x;
    if (w >= nwords) return;
    unsigned long long cur = g_bits[w];
    if (!cur) return;
    int base = w << 6;
    unsigned long long r = cur & ~(cur << 1);
    while (r) {
        int k = __ffsll((long long)r) - 1;
        r &= r - 1;
        int node = base + k;
        int root = find_root(node);
        if (root != node) g_label[node] = root;   // compress to final root
        atomicAdd(&g_area[root], run_len(cur, k));
    }
}

// ---------------------------------------------------------------------------
// k_bce: fused loss — per-word, per-run root/area lookup, no label image
// ---------------------------------------------------------------------------
__device__ __forceinline__ double warp_sum(double v) {
#pragma unroll
    for (int off = 16; off > 0; off >>= 1)
        v += __shfl_down_sync(0xFFFFFFFFu, v, off);
    return v;
}

__global__ void k_bce(const float* __restrict__ in, int nwords) {
    double s0 = 0.0, s1 = 0.0, s2 = 0.0, s3 = 0.0;
    int w = blockIdx.x * blockDim.x + threadIdx.x;
    if (w < nwords) {
        unsigned long long cur = g_bits[w];
        int base = w << 6;
        const float4* in4 = (const float4*)in;

        float f0 = 0.f, f1 = 0.f, f2 = 0.f, f3 = 0.f;
        float wgt = 0.f, inv = 0.f;   // carried across current run

#pragma unroll
        for (int c = 0; c < 4; c++) {
            float4 v[4];
#pragma unroll
            for (int g = 0; g < 4; g++)
                v[g] = __ldg(&in4[w * 16 + c * 4 + g]);
#pragma unroll
            for (int g = 0; g < 4; g++) {
                float xs[4] = {v[g].x, v[g].y, v[g].z, v[g].w};
#pragma unroll
                for (int lane = 0; lane < 4; lane++) {
                    int k = (c * 4 + g) * 4 + lane;
                    float x = xs[lane];
                    float gpl = __logf(1.f + __expf(-fabsf(x)));
                    bool fg = (cur >> k) & 1ull;
                    if (fg) {
                        bool start = (k == 0) || !((cur >> (k - 1)) & 1ull);
                        if (start) {
                            int root = g_label[base + k];      // compressed
                            float area = (float)__ldg(&g_area[root]);
                            wgt = sqrtf(area);
                            inv = __fdividef(1.f, wgt + 1.f);
                        }
                        float bce = fmaxf(-x, 0.f) + gpl;
                        f0 += bce * inv;
                        f2 += wgt;
                        f3 += 1.f;
                    } else {
                        f1 += fmaxf(x, 0.f) + gpl;
                    }
                }
            }
        }
        s0 = f0; s1 = f1; s2 = f2; s3 = f3;
    }

    __shared__ double sh[4][8];
    int lane = threadIdx.x & 31;
    int warp = threadIdx.x >> 5;
    s0 = warp_sum(s0); s1 = warp_sum(s1); s2 = warp_sum(s2); s3 = warp_sum(s3);
    if (lane == 0) { sh[0][warp] = s0; sh[1][warp] = s1; sh[2][warp] = s2; sh[3][warp] = s3; }
    __syncthreads();
    int nw = blockDim.x >> 5;
    if (warp == 0) {
        double v0 = (lane < nw) ? sh[0][lane] : 0.0;
        double v1 = (lane < nw) ? sh[1][lane] : 0.0;
        double v2 = (lane < nw) ? sh[2][lane] : 0.0;
        double v3 = (lane < nw) ? sh[3][lane] : 0.0;
        v0 = warp_sum(v0); v1 = warp_sum(v1); v2 = warp_sum(v2); v3 = warp_sum(v3);
        if (lane == 0) {
            atomicAdd(&g_acc[0], v0);
            atomicAdd(&g_acc[1], v1);
            atomicAdd(&g_acc[2], v2);
            atomicAdd(&g_acc[3], v3);
        }
    }
}

__global__ void k_final(float* __restrict__ out, double inv_n) {
    double nfg = g_acc[3];
    double mean_nz = g_acc[2] / (nfg > 0.0 ? nfg : 1.0);
    double loss = (g_acc[0] + g_acc[1] / (mean_nz + 1.0)) * inv_n;
    out[0] = (float)loss;
}

// ---------------------------------------------------------------------------
extern "C" void kernel_launch(void* const* d_in, const int* in_sizes, int n_in,
                              void* d_out, int out_size) {
    const float* inputs  = (const float*)d_in[0];
    const float* targets = (const float*)d_in[1];
    float* out = (float*)d_out;

    int n = in_sizes[0];
    int nwords = n >> 6;
    const int threads = 256;
    int wblocks = (nwords + threads - 1) / threads;

    k_prep<<<wblocks, threads>>>(targets, nwords);
    k_union<<<wblocks, threads>>>(nwords);
    k_area<<<wblocks, threads>>>(nwords);
    k_bce<<<wblocks, threads>>>(inputs, nwords);
    k_final<<<1, 1>>>(out, 1.0 / (double)n);
}

// round 5
// speedup vs baseline: 2.2587x; 1.1899x over previous
#include <cuda_runtime.h>
#include <math.h>

#define W_IMG 512
#define H_IMG 512
#define HW_IMG (W_IMG * H_IMG)
#define MAX_N (32 * HW_IMG)
#define MAX_WORDS (MAX_N / 64)

// Scratch (no cudaMalloc allowed)
__device__ int g_label[MAX_N];                    // UF parent (run-start nodes only)
__device__ int g_area[MAX_N];                     // per-root component area
__device__ unsigned long long g_bits[MAX_WORDS];  // fg bitmask, 64 px/word
// 0 = sum_fg bce/(w+1), 1 = sum_bg bce, 2 = sum_fg w, 3 = N_fg
__device__ double g_acc[4];

// ---------------------------------------------------------------------------
// Union-find (labels only decrease -> atomicMin union converges in one pass)
// ---------------------------------------------------------------------------
__device__ __forceinline__ int find_root(int x) {
    int p = g_label[x];
    while (p != x) { x = p; p = g_label[x]; }
    return x;
}

__device__ __forceinline__ void merge(int a, int b) {
    bool done = false;
    do {
        a = find_root(a);
        b = find_root(b);
        if (a < b) { int t = a; a = b; b = t; }
        if (a != b) {
            int old = atomicMin(&g_label[a], b);
            done = (old == a);
            a = old;
        } else {
            done = true;
        }
    } while (!done);
}

// Run start (bit position) of the run containing set bit k of mask m.
__device__ __forceinline__ int rs_in_word(unsigned long long m, int k) {
    unsigned long long below = (k == 0) ? 0ull : ((1ull << k) - 1ull);
    unsigned long long z = (~m) & below;
    return z ? (64 - __clzll(z)) : 0;
}

// Length of the run of ones in m starting at bit k.
__device__ __forceinline__ int run_len(unsigned long long m, int k) {
    unsigned long long inv = ~(m >> k);
    return inv ? (__ffsll((long long)inv) - 1) : (64 - k);
}

// ---------------------------------------------------------------------------
// k_prep: thread per 16-px segment. Build word mask cooperatively (shfl),
// init UF nodes + areas at run starts within own segment.
// ---------------------------------------------------------------------------
__global__ void k_prep(const float* __restrict__ tgt, int nseg) {
    int t = blockIdx.x * blockDim.x + threadIdx.x;
    if (t < nseg) {
        int w = t >> 2;
        int seg = t & 3;
        int s0 = seg << 4;
        const float4* t4 = (const float4*)tgt;
        int gbase = w * 16 + seg * 4;

        unsigned long long piece = 0ull;
#pragma unroll
        for (int g = 0; g < 4; g++) {
            float4 v = __ldg(&t4[gbase + g]);
            unsigned long long nib = 0ull;
            if (v.x > 0.f) nib |= 1ull;
            if (v.y > 0.f) nib |= 2ull;
            if (v.z > 0.f) nib |= 4ull;
            if (v.w > 0.f) nib |= 8ull;
            piece |= nib << (g * 4);
        }
        unsigned long long m = piece << s0;
        // assemble full 64-bit word across the aligned 4-lane group
        m |= __shfl_xor_sync(0xFFFFFFFFu, m, 1);
        m |= __shfl_xor_sync(0xFFFFFFFFu, m, 2);
        if (seg == 0) g_bits[w] = m;

        // run starts within my segment
        unsigned long long starts = (m & ~(m << 1)) >> s0;
        unsigned int r = (unsigned int)(starts & 0xFFFFull);
        int base = (w << 6) + s0;
        while (r) {
            int k = __ffs(r) - 1;
            r &= r - 1;
            g_label[base + k] = base + k;
            g_area[base + k] = 0;
        }
    }
    if (blockIdx.x == 0 && threadIdx.x < 4) g_acc[threadIdx.x] = 0.0;
}

// ---------------------------------------------------------------------------
// k_union: word-level bitmask merges (cheap; ~12k horizontal, ~700k vertical)
// ---------------------------------------------------------------------------
__global__ void k_union(int nwords) {
    int w = blockIdx.x * blockDim.x + threadIdx.x;
    if (w >= nwords) return;
    unsigned long long cur = g_bits[w];
    if (!cur) return;
    int base = w << 6;
    int wx = w & 7;
    int wy = (w >> 3) & (H_IMG - 1);

    if (wx && (cur & 1ull)) {
        unsigned long long L = g_bits[w - 1];
        if (L >> 63) merge(base, ((w - 1) << 6) + rs_in_word(L, 63));
    }
    if (wy) {
        unsigned long long up = g_bits[w - 8];
        unsigned long long ov = cur & up;
        unsigned long long need = ov & ~(ov << 1);
        while (need) {
            int k = __ffsll((long long)need) - 1;
            need &= need - 1;
            merge(base + rs_in_word(cur, k),
                  ((w - 8) << 6) + rs_in_word(up, k));
        }
    }
}

// ---------------------------------------------------------------------------
// k_area: thread per segment; run-starts in segment -> compress + area add
// ---------------------------------------------------------------------------
__global__ void k_area(int nseg) {
    int t = blockIdx.x * blockDim.x + threadIdx.x;
    if (t >= nseg) return;
    int w = t >> 2;
    int seg = t & 3;
    int s0 = seg << 4;
    unsigned long long cur = g_bits[w];
    unsigned int starts = (unsigned int)(((cur & ~(cur << 1)) >> s0) & 0xFFFFull);
    if (!starts) return;
    int base = w << 6;
    while (starts) {
        int k = __ffs(starts) - 1;
        starts &= starts - 1;
        int kk = s0 + k;
        int node = base + kk;
        int root = find_root(node);
        if (root != node) g_label[node] = root;   // compress to final root
        atomicAdd(&g_area[root], run_len(cur, kk));
    }
}

// ---------------------------------------------------------------------------
// k_bce: thread per 16-px segment; run-entry root/area lookup via word mask
// ---------------------------------------------------------------------------
__device__ __forceinline__ double warp_sum(double v) {
#pragma unroll
    for (int off = 16; off > 0; off >>= 1)
        v += __shfl_down_sync(0xFFFFFFFFu, v, off);
    return v;
}

__global__ void k_bce(const float* __restrict__ in, int nseg) {
    double s0d = 0.0, s1d = 0.0, s2d = 0.0, s3d = 0.0;
    int t = blockIdx.x * blockDim.x + threadIdx.x;
    if (t < nseg) {
        int w = t >> 2;
        int seg = t & 3;
        int s0 = seg << 4;
        unsigned long long cur = __ldg(&g_bits[w]);
        int base = w << 6;
        const float4* in4 = (const float4*)in;
        int gbase = w * 16 + seg * 4;

        float4 v[4];
#pragma unroll
        for (int g = 0; g < 4; g++) v[g] = __ldg(&in4[gbase + g]);

        float f0 = 0.f, f1 = 0.f, f2 = 0.f, f3 = 0.f;
        float wgt = 0.f, inv = 0.f;
        bool prev_fg = false;

#pragma unroll
        for (int g = 0; g < 4; g++) {
            float xs[4] = {v[g].x, v[g].y, v[g].z, v[g].w};
#pragma unroll
            for (int lane = 0; lane < 4; lane++) {
                int k = s0 + g * 4 + lane;
                float x = xs[lane];
                float gpl = __logf(1.f + __expf(-fabsf(x)));
                bool fg = (cur >> k) & 1ull;
                if (fg) {
                    if (!prev_fg) {
                        int rs = rs_in_word(cur, k);
                        int root = __ldg(&g_label[base + rs]);  // compressed
                        float area = (float)__ldg(&g_area[root]);
                        wgt = sqrtf(area);
                        inv = __fdividef(1.f, wgt + 1.f);
                    }
                    f0 += (fmaxf(-x, 0.f) + gpl) * inv;
                    f2 += wgt;
                    f3 += 1.f;
                } else {
                    f1 += fmaxf(x, 0.f) + gpl;
                }
                prev_fg = fg;
            }
        }
        s0d = f0; s1d = f1; s2d = f2; s3d = f3;
    }

    __shared__ double sh[4][8];
    int lane = threadIdx.x & 31;
    int warp = threadIdx.x >> 5;
    s0d = warp_sum(s0d); s1d = warp_sum(s1d); s2d = warp_sum(s2d); s3d = warp_sum(s3d);
    if (lane == 0) { sh[0][warp] = s0d; sh[1][warp] = s1d; sh[2][warp] = s2d; sh[3][warp] = s3d; }
    __syncthreads();
    int nw = blockDim.x >> 5;
    if (warp == 0) {
        double v0 = (lane < nw) ? sh[0][lane] : 0.0;
        double v1 = (lane < nw) ? sh[1][lane] : 0.0;
        double v2 = (lane < nw) ? sh[2][lane] : 0.0;
        double v3 = (lane < nw) ? sh[3][lane] : 0.0;
        v0 = warp_sum(v0); v1 = warp_sum(v1); v2 = warp_sum(v2); v3 = warp_sum(v3);
        if (lane == 0) {
            atomicAdd(&g_acc[0], v0);
            atomicAdd(&g_acc[1], v1);
            atomicAdd(&g_acc[2], v2);
            atomicAdd(&g_acc[3], v3);
        }
    }
}

__global__ void k_final(float* __restrict__ out, double inv_n) {
    double nfg = g_acc[3];
    double mean_nz = g_acc[2] / (nfg > 0.0 ? nfg : 1.0);
    double loss = (g_acc[0] + g_acc[1] / (mean_nz + 1.0)) * inv_n;
    out[0] = (float)loss;
}

// ---------------------------------------------------------------------------
extern "C" void kernel_launch(void* const* d_in, const int* in_sizes, int n_in,
                              void* d_out, int out_size) {
    const float* inputs  = (const float*)d_in[0];
    const float* targets = (const float*)d_in[1];
    float* out = (float*)d_out;

    int n = in_sizes[0];
    int nwords = n >> 6;
    int nseg = n >> 4;
    const int threads = 256;
    int wblocks = (nwords + threads - 1) / threads;
    int sblocks = (nseg + threads - 1) / threads;

    k_prep<<<sblocks, threads>>>(targets, nseg);
    k_union<<<wblocks, threads>>>(nwords);
    k_area<<<sblocks, threads>>>(nseg);
    k_bce<<<sblocks, threads>>>(inputs, nseg);
    k_final<<<1, 1>>>(out, 1.0 / (double)n);
}